// round 8
// baseline (speedup 1.0000x reference)
#include <cuda_runtime.h>
#include <cuda_bf16.h>
#include <math.h>
#include <stdint.h>

// Fixed problem shape: n=8192, k=128, h=128
#define N_FIX 8192
#define KDIM 128
#define BM 32
#define BK 32
#define NITER (N_FIX / BK)   // 256
#define NCTA (N_FIX / BM)    // 256
// dynamic smem: B stages [0,32768) 4 x 8KB ; A bufs [32768, +2*2560)
#define ABASE 32768
#define ABUF 2560            // 32 rows x 80B (bf16 row 64B padded to 80)
#define SMEM_BYTES (32768 + 2 * ABUF)

// ---------------- device scratch ----------------
__device__ __align__(16) __nv_bfloat16 g_Cb[(size_t)N_FIX * KDIM];
__device__ float g_col[KDIM];
__device__ float g_diag[KDIM];
__device__ float g_sA;
__device__ float g_hpart;
__device__ int g_cnt;

// ---------------- helpers ----------------
__device__ __forceinline__ uint32_t smem_u32(const void* p) {
    uint32_t a;
    asm("{ .reg .u64 t; cvta.to.shared.u64 t, %1; cvt.u32.u64 %0, t; }" : "=r"(a) : "l"(p));
    return a;
}
__device__ __forceinline__ void cp16(uint32_t saddr, const void* gp) {
    unsigned long long g = __cvta_generic_to_global(gp);
    asm volatile("cp.async.cg.shared.global [%0], [%1], 16;" :: "r"(saddr), "l"(g) : "memory");
}
#define CP_COMMIT() asm volatile("cp.async.commit_group;" ::: "memory")
#define CP_WAIT2()  asm volatile("cp.async.wait_group 2;" ::: "memory")

__device__ __forceinline__ uint32_t cvt_bf2(float x, float y) {
    uint32_t r;  // low = x, high = y
    asm("cvt.rn.bf16x2.f32 %0, %1, %2;" : "=r"(r) : "f"(y), "f"(x));
    return r;
}
__device__ __forceinline__ void ldmx4(uint32_t* r, uint32_t addr) {
    asm volatile("ldmatrix.sync.aligned.m8n8.x4.shared.b16 {%0,%1,%2,%3}, [%4];"
                 : "=r"(r[0]), "=r"(r[1]), "=r"(r[2]), "=r"(r[3]) : "r"(addr));
}
__device__ __forceinline__ void ldmx4t(uint32_t& r0, uint32_t& r1, uint32_t& r2,
                                       uint32_t& r3, uint32_t addr) {
    asm volatile("ldmatrix.sync.aligned.m8n8.x4.trans.shared.b16 {%0,%1,%2,%3}, [%4];"
                 : "=r"(r0), "=r"(r1), "=r"(r2), "=r"(r3) : "r"(addr));
}
__device__ __forceinline__ void mma16816(float* d, const uint32_t* a, uint32_t b0,
                                         uint32_t b1) {
    asm volatile(
        "mma.sync.aligned.m16n8k16.row.col.f32.bf16.bf16.f32 "
        "{%0,%1,%2,%3}, {%4,%5,%6,%7}, {%8,%9}, {%0,%1,%2,%3};"
        : "+f"(d[0]), "+f"(d[1]), "+f"(d[2]), "+f"(d[3])
        : "r"(a[0]), "r"(a[1]), "r"(a[2]), "r"(a[3]), "r"(b0), "r"(b1));
}

// ---------------- C -> bf16 + global init ----------------
__global__ void __launch_bounds__(256) k_prep(const float* __restrict__ C) {
    if (blockIdx.x == 0) {
        int t = threadIdx.x;
        if (t < KDIM) { g_col[t] = 0.0f; g_diag[t] = 0.0f; }
        if (t == 0) { g_sA = 0.0f; g_hpart = 0.0f; g_cnt = 0; }
    }
    size_t base = ((size_t)blockIdx.x * 256 + threadIdx.x) * 16;
    const float4* src = reinterpret_cast<const float4*>(C + base);
    uint32_t o[8];
#pragma unroll
    for (int q = 0; q < 4; ++q) {
        float4 v = __ldg(&src[q]);
        o[q * 2 + 0] = cvt_bf2(v.x, v.y);
        o[q * 2 + 1] = cvt_bf2(v.z, v.w);
    }
    uint4* dst = reinterpret_cast<uint4*>(g_Cb + base);
    dst[0] = make_uint4(o[0], o[1], o[2], o[3]);
    dst[1] = make_uint4(o[4], o[5], o[6], o[7]);
}

// ---------------- fully fused GEMM + all reductions + final ----------------
__global__ void __launch_bounds__(256, 2) k_gemm(const float* __restrict__ A,
                                                 const float* __restrict__ C,
                                                 const float* __restrict__ H,
                                                 const float* __restrict__ papra,
                                                 const int* __restrict__ flag,
                                                 float* __restrict__ out, int out_size) {
    extern __shared__ __align__(1024) char smem[];
    __shared__ float scol[KDIM], sdiag[KDIM], srow[BM], swarp[4];
    __shared__ int is_last;

    const int tid = threadIdx.x, lane = tid & 31, wid = tid >> 5;
    const int wm = wid & 1, wn = wid >> 1;   // 2 M-warps (m16) x 4 N-warps (n32)
    const int blockRow = blockIdx.x * BM;
    const uint32_t su = smem_u32(smem);

    if (tid < KDIM) { scol[tid] = 0.0f; sdiag[tid] = 0.0f; }

    // ---- A load mapping: 32 rows x 32 fp32 per tile; 8 threads/row, 4 floats each
    const int arow = tid >> 3;
    const int acol = (tid & 7) * 4;
    const float* gA = A + (size_t)(blockRow + arow) * N_FIX + acol;
    char* aST = smem + ABASE + arow * 80 + acol * 2;  // bf16: 2B/elem

    // ---- B cp.async mapping: 8KB/tile = 512 chunks, 2 per thread
    const int ch0 = tid, ch1 = tid + 256;
    const int kB0 = ch0 >> 4, cB0 = ch0 & 15;
    const int kB1 = ch1 >> 4, cB1 = ch1 & 15;
    const uint32_t sB0 = (uint32_t)(kB0 * 256 + ((cB0 ^ (kB0 & 7)) << 4));
    const uint32_t sB1 = (uint32_t)(kB1 * 256 + ((cB1 ^ (kB1 & 7)) << 4));
    const __nv_bfloat16* gB0 = g_Cb + kB0 * KDIM + cB0 * 8;
    const __nv_bfloat16* gB1 = g_Cb + kB1 * KDIM + cB1 * 8;

    // ---- LDSM A offsets [kq] (80B row stride; 5 coprime 8 -> conflict-free)
    uint32_t aoff[2];
    {
        int r = wm * 16 + (lane & 15);
        int kh = lane >> 4;  // k-half within k16
#pragma unroll
        for (int kq = 0; kq < 2; ++kq)
            aoff[kq] = su + ABASE + (uint32_t)(r * 80 + (kq * 2 + kh) * 16);
    }
    // ---- LDSM B (trans) offsets [g][kq]
    uint32_t boff[2][2];
    {
        int mM = lane >> 3, iR = lane & 7;
        int kkb = (mM & 1) * 8 + iR;
#pragma unroll
        for (int g = 0; g < 2; ++g)
#pragma unroll
            for (int kq = 0; kq < 2; ++kq) {
                int k = kq * 16 + kkb;
                int nn = wn * 32 + g * 16 + (mM >> 1) * 8;
                uint32_t off = (uint32_t)(k * 256 + nn * 2);
                boff[g][kq] = su + (off ^ ((k & 7) << 4));
            }
    }

    float acc[4][4];
#pragma unroll
    for (int nt = 0; nt < 4; ++nt)
#pragma unroll
        for (int e = 0; e < 4; ++e) acc[nt][e] = 0.0f;
    float dsum = 0.0f;

    // ---- A register pipeline, depth 4: ab[t%4] holds tile t (1 float4/thread)
    float4 ab[4];
#pragma unroll
    for (int s = 0; s < 4; ++s)
        ab[s] = __ldg(reinterpret_cast<const float4*>(gA + (size_t)s * BK));
    {   // STS tile 0
        dsum += (ab[0].x + ab[0].y) + (ab[0].z + ab[0].w);
        uint2 st = make_uint2(cvt_bf2(ab[0].x, ab[0].y), cvt_bf2(ab[0].z, ab[0].w));
        *reinterpret_cast<uint2*>(aST) = st;
    }
    // B stages 0..2
#pragma unroll
    for (int s = 0; s < 3; ++s) {
        cp16(su + s * 8192 + sB0, gB0 + (size_t)s * 4096);
        cp16(su + s * 8192 + sB1, gB1 + (size_t)s * 4096);
        CP_COMMIT();
    }

    // ---- main loop (unroll 4 so rotating indices constant-fold) ----
#pragma unroll 4
    for (int it = 0; it < NITER; ++it) {
        CP_WAIT2();
        __syncthreads();
        const uint32_t abuf = (uint32_t)((it & 1) * ABUF);
        const uint32_t sst = (uint32_t)((it & 3) * 8192);

        // refill A register slot with tile it+4
        const int fit = it + 4;
        if (fit < NITER)
            ab[it & 3] = __ldg(reinterpret_cast<const float4*>(gA + (size_t)fit * BK));
        // B prefetch stage it+3
        const int pit = it + 3;
        if (pit < NITER) {
            uint32_t sb = su + (pit & 3) * 8192;
            cp16(sb + sB0, gB0 + (size_t)pit * 4096);
            cp16(sb + sB1, gB1 + (size_t)pit * 4096);
        }
        CP_COMMIT();

#pragma unroll
        for (int kq = 0; kq < 2; ++kq) {
            uint32_t ra[4];
            ldmx4(ra, aoff[kq] + abuf);
#pragma unroll
            for (int g = 0; g < 2; ++g) {
                uint32_t b0, b1, b2, b3;
                ldmx4t(b0, b1, b2, b3, boff[g][kq] + sst);
                mma16816(acc[2 * g], ra, b0, b1);
                mma16816(acc[2 * g + 1], ra, b2, b3);
            }
        }

        // STS tile it+1 (loaded 3+ iterations ago -> latency covered)
        const int nit = it + 1;
        if (nit < NITER) {
            const float4 na = ab[nit & 3];
            dsum += (na.x + na.y) + (na.z + na.w);
            uint2 st = make_uint2(cvt_bf2(na.x, na.y), cvt_bf2(na.z, na.w));
            *reinterpret_cast<uint2*>(aST + (nit & 1) * ABUF) = st;
        }
    }

    // ---- row sums (exact fp32) into smem (8 threads/row) ----
    dsum += __shfl_xor_sync(0xffffffffu, dsum, 1);
    dsum += __shfl_xor_sync(0xffffffffu, dsum, 2);
    dsum += __shfl_xor_sync(0xffffffffu, dsum, 4);
    if ((tid & 7) == 0) srow[arow] = dsum;

    // ---- colsum(M) and diag = sum_i C[i][j]*M[i][j] ----
#pragma unroll
    for (int nt = 0; nt < 4; ++nt) {
        const int col = wn * 32 + nt * 8 + (lane & 3) * 2;
        const int r0 = blockRow + wm * 16 + (lane >> 2);
        float2 c00 = *reinterpret_cast<const float2*>(C + (size_t)r0 * KDIM + col);
        float2 c08 = *reinterpret_cast<const float2*>(C + (size_t)(r0 + 8) * KDIM + col);
        float cs0 = acc[nt][0] + acc[nt][2];
        float cs1 = acc[nt][1] + acc[nt][3];
        float ds0 = c00.x * acc[nt][0] + c08.x * acc[nt][2];
        float ds1 = c00.y * acc[nt][1] + c08.y * acc[nt][3];
#pragma unroll
        for (int o = 4; o <= 16; o <<= 1) {
            cs0 += __shfl_xor_sync(0xffffffffu, cs0, o);
            cs1 += __shfl_xor_sync(0xffffffffu, cs1, o);
            ds0 += __shfl_xor_sync(0xffffffffu, ds0, o);
            ds1 += __shfl_xor_sync(0xffffffffu, ds1, o);
        }
        if (lane < 4) {
            const int cc = wn * 32 + nt * 8 + lane * 2;
            atomicAdd(&scol[cc], cs0);
            atomicAdd(&scol[cc + 1], cs1);
            atomicAdd(&sdiag[cc], ds0);
            atomicAdd(&sdiag[cc + 1], ds1);
        }
    }
    __syncthreads();
    if (tid < KDIM) {
        atomicAdd(&g_col[tid], scol[tid]);
        atomicAdd(&g_diag[tid], sdiag[tid]);
    }

    // ---- h_part + sA for this CTA's 32 rows ----
    {
        const float4* hp = reinterpret_cast<const float4*>(
            H + (size_t)(blockRow + arow) * KDIM + (tid & 7) * 16);
        float h2 = 0.0f;
#pragma unroll
        for (int q = 0; q < 4; ++q) {
            float4 v = __ldg(&hp[q]);
            h2 += v.x * v.x + v.y * v.y + v.z * v.z + v.w * v.w;
        }
        h2 += __shfl_xor_sync(0xffffffffu, h2, 1);
        h2 += __shfl_xor_sync(0xffffffffu, h2, 2);
        h2 += __shfl_xor_sync(0xffffffffu, h2, 4);
        __syncthreads();  // srow ready
        if ((tid & 7) == 0) {
            float d = srow[arow];
            srow[arow] = 0.0f;  // reuse below via atomics? no — store pair in regs
            // store products back: use swarp-free path: lane writes into scol? no.
            // Simply: each leader thread atomically adds to globals via warp agg below.
            sdiag[arow] = d;          // reuse sdiag[0..31] as scratch for d
            scol[arow] = d * h2;      // reuse scol[0..31] as scratch for d*h2
        }
        __syncthreads();
        if (tid < 32) {
            float a1 = scol[tid];
            float a2 = sdiag[tid];
#pragma unroll
            for (int o = 16; o > 0; o >>= 1) {
                a1 += __shfl_xor_sync(0xffffffffu, a1, o);
                a2 += __shfl_xor_sync(0xffffffffu, a2, o);
            }
            if (tid == 0) {
                atomicAdd(&g_hpart, a1);
                atomicAdd(&g_sA, a2);
            }
        }
    }

    // ---- last CTA computes final scalars ----
    if (tid == 0) {
        __threadfence();
        int c = atomicAdd(&g_cnt, 1);
        is_last = (c == NCTA - 1);
    }
    __syncthreads();
    if (is_last) {
        float t = 0.0f;
        float sA = *(volatile float*)&g_sA;
        if (tid < KDIM) {
            float dg = *(volatile float*)&g_diag[tid];
            float cl = *(volatile float*)&g_col[tid];
            t = dg * log2f(cl / sA + 1e-40f);
        }
#pragma unroll
        for (int o = 16; o > 0; o >>= 1) t += __shfl_xor_sync(0xffffffffu, t, o);
        if (lane == 0 && wid < 4) swarp[wid] = t;
        __syncthreads();
        if (tid == 0) {
            float total = (swarp[0] + swarp[1] + swarp[2] + swarp[3]) / sA;
            float hp = *(volatile float*)&g_hpart;
            int fl = flag ? *flag : 20;
            float pw = papra ? *papra : 1.0f;
            if (fl > 10) total += pw * hp;
            out[0] = total;
            if (out_size > 1) out[1] = hp;
        }
    }
}

extern "C" void kernel_launch(void* const* d_in, const int* in_sizes, int n_in,
                              void* d_out, int out_size) {
    const float* A = (const float*)d_in[0];
    const float* C = (const float*)d_in[1];
    const float* H = (const float*)d_in[2];
    const float* papra = (n_in > 3) ? (const float*)d_in[3] : nullptr;
    const int* flag = (n_in > 4) ? (const int*)d_in[4] : nullptr;

    cudaFuncSetAttribute(k_gemm, cudaFuncAttributeMaxDynamicSharedMemorySize, SMEM_BYTES);

    k_prep<<<(N_FIX * KDIM) / (256 * 16), 256>>>(C);
    k_gemm<<<NCTA, 256, SMEM_BYTES>>>(A, C, H, papra, flag, (float*)d_out, out_size);
}

// round 9
// speedup vs baseline: 1.6076x; 1.6076x over previous
#include <cuda_runtime.h>
#include <cuda_bf16.h>
#include <math.h>
#include <stdint.h>

// Fixed problem shape: n=8192, k=128, h=128
#define N_FIX 8192
#define KDIM 128
#define BM 64
#define BK 32
#define KSPLIT 2
#define KHALF (N_FIX / KSPLIT)        // 4096
#define NIT (KHALF / BK)              // 128 iterations per CTA
#define NCTA ((N_FIX / BM) * KSPLIT)  // 256
#define STAGES 4
#define STAGE_BYTES 16384             // 8KB A (64x32 fp32) + 8KB B (32x128 bf16)
#define SMEM_BYTES (STAGES * STAGE_BYTES)

// ---------------- device scratch ----------------
__device__ __align__(16) __nv_bfloat16 g_Cb[(size_t)N_FIX * KDIM];
__device__ float g_d[N_FIX];     // row sums of A (atomic, 2 partials)
__device__ float g_h2[N_FIX];    // ||H_i||^2
__device__ float g_col[KDIM];
__device__ float g_diag[KDIM];
__device__ int g_cnt;

// ---------------- helpers ----------------
__device__ __forceinline__ uint32_t smem_u32(const void* p) {
    uint32_t a;
    asm("{ .reg .u64 t; cvta.to.shared.u64 t, %1; cvt.u32.u64 %0, t; }" : "=r"(a) : "l"(p));
    return a;
}
__device__ __forceinline__ void cp16(uint32_t saddr, const void* gp) {
    unsigned long long g = __cvta_generic_to_global(gp);
    asm volatile("cp.async.cg.shared.global [%0], [%1], 16;" :: "r"(saddr), "l"(g) : "memory");
}
#define CP_COMMIT() asm volatile("cp.async.commit_group;" ::: "memory")
#define CP_WAIT2()  asm volatile("cp.async.wait_group 2;" ::: "memory")

__device__ __forceinline__ uint32_t cvt_bf2(float2 v) {
    uint32_t r;  // low = v.x, high = v.y
    asm("cvt.rn.bf16x2.f32 %0, %1, %2;" : "=r"(r) : "f"(v.y), "f"(v.x));
    return r;
}
__device__ __forceinline__ void ldmx4t(uint32_t& r0, uint32_t& r1, uint32_t& r2,
                                       uint32_t& r3, uint32_t addr) {
    asm volatile("ldmatrix.sync.aligned.m8n8.x4.trans.shared.b16 {%0,%1,%2,%3}, [%4];"
                 : "=r"(r0), "=r"(r1), "=r"(r2), "=r"(r3) : "r"(addr));
}
__device__ __forceinline__ void mma16816(float* d, const uint32_t* a, uint32_t b0,
                                         uint32_t b1) {
    asm volatile(
        "mma.sync.aligned.m16n8k16.row.col.f32.bf16.bf16.f32 "
        "{%0,%1,%2,%3}, {%4,%5,%6,%7}, {%8,%9}, {%0,%1,%2,%3};"
        : "+f"(d[0]), "+f"(d[1]), "+f"(d[2]), "+f"(d[3])
        : "r"(a[0]), "r"(a[1]), "r"(a[2]), "r"(a[3]), "r"(b0), "r"(b1));
}

// ---------------- prep: init, C->bf16, ||H_i||^2 ----------------
// grid = 256 blocks x 256 threads. Block b owns rows [32b, 32b+32).
__global__ void __launch_bounds__(256) k_prep(const float* __restrict__ C,
                                              const float* __restrict__ H) {
    const int b = blockIdx.x, tid = threadIdx.x;
    if (b == 0) {
        if (tid < KDIM) { g_col[tid] = 0.0f; g_diag[tid] = 0.0f; }
        if (tid == 0) g_cnt = 0;
    }
    if (tid < 32) g_d[b * 32 + tid] = 0.0f;

    // C -> bf16 (16 elems/thread)
    size_t base = ((size_t)b * 256 + tid) * 16;
    const float4* src = reinterpret_cast<const float4*>(C + base);
    uint32_t o[8];
#pragma unroll
    for (int q = 0; q < 4; ++q) {
        float4 v = __ldg(&src[q]);
        o[q * 2 + 0] = cvt_bf2(make_float2(v.x, v.y));
        o[q * 2 + 1] = cvt_bf2(make_float2(v.z, v.w));
    }
    uint4* dst = reinterpret_cast<uint4*>(g_Cb + base);
    dst[0] = make_uint4(o[0], o[1], o[2], o[3]);
    dst[1] = make_uint4(o[4], o[5], o[6], o[7]);

    // h2 for rows [32b, 32b+32): 8 threads/row, 16 floats each
    const int row = b * 32 + (tid >> 3);
    const float4* hp = reinterpret_cast<const float4*>(H + (size_t)row * KDIM + (tid & 7) * 16);
    float h2 = 0.0f;
#pragma unroll
    for (int q = 0; q < 4; ++q) {
        float4 v = __ldg(&hp[q]);
        h2 += v.x * v.x + v.y * v.y + v.z * v.z + v.w * v.w;
    }
    h2 += __shfl_xor_sync(0xffffffffu, h2, 1);
    h2 += __shfl_xor_sync(0xffffffffu, h2, 2);
    h2 += __shfl_xor_sync(0xffffffffu, h2, 4);
    if ((tid & 7) == 0) g_h2[row] = h2;
}

// ---------------- split-K GEMM + fused reductions + final ----------------
__global__ void __launch_bounds__(256, 2) k_gemm(const float* __restrict__ A,
                                                 const float* __restrict__ C,
                                                 const float* __restrict__ papra,
                                                 const int* __restrict__ flag,
                                                 float* __restrict__ out, int out_size) {
    extern __shared__ __align__(1024) char smem[];
    __shared__ float scol[KDIM], sdiag[KDIM], swarp[8];
    __shared__ int is_last;

    const int tid = threadIdx.x, lane = tid & 31, wid = tid >> 5;
    const int wm = wid & 3, wn = wid >> 2;        // 4 M-warps x 2 N-warps
    const int rb = blockIdx.x >> 1;               // row block 0..127
    const int kh = blockIdx.x & 1;                // K half 0/1
    const int blockRow = rb * BM;
    const int kbase = kh * KHALF;
    const uint32_t su = smem_u32(smem);

    if (tid < KDIM) { scol[tid] = 0.0f; sdiag[tid] = 0.0f; }

    // ---- cp.async chunk mapping (2 A-chunks + 2 B-chunks per thread) ----
    const int chA0 = tid, chA1 = tid + 256;
    const int rA0 = chA0 >> 3, cA0 = chA0 & 7;
    const int rA1 = chA1 >> 3, cA1 = chA1 & 7;
    const uint32_t soA0 = (uint32_t)(chA0 * 16) ^ ((rA0 & 7) << 4);
    const uint32_t soA1 = (uint32_t)(chA1 * 16) ^ ((rA1 & 7) << 4);
    const float* gA0 = A + (size_t)(blockRow + rA0) * N_FIX + kbase + cA0 * 4;
    const float* gA1 = A + (size_t)(blockRow + rA1) * N_FIX + kbase + cA1 * 4;

    const int kB0 = chA0 >> 4, cB0 = chA0 & 15;
    const int kB1 = chA1 >> 4, cB1 = chA1 & 15;
    const uint32_t soB0 = (uint32_t)(chA0 * 16) ^ ((kB0 & 7) << 4);
    const uint32_t soB1 = (uint32_t)(chA1 * 16) ^ ((kB1 & 7) << 4);
    const __nv_bfloat16* gB0 = g_Cb + (size_t)(kbase + kB0) * KDIM + cB0 * 8;
    const __nv_bfloat16* gB1 = g_Cb + (size_t)(kbase + kB1) * KDIM + cB1 * 8;

    // ---- fragment smem offsets ----
    const int r0 = wm * 16 + (lane >> 2);
    const int cb = (lane & 3) * 2;
    uint32_t aoff[2][4];
#pragma unroll
    for (int kq = 0; kq < 2; ++kq) {
        int cc = kq * 16 + cb;
#pragma unroll
        for (int q = 0; q < 4; ++q) {
            int rr = r0 + ((q & 1) ? 8 : 0);
            int c2 = cc + ((q & 2) ? 8 : 0);
            uint32_t off = (uint32_t)(rr * 128 + c2 * 4);
            aoff[kq][q] = off ^ ((rr & 7) << 4);
        }
    }
    uint32_t boff[4];
    {
        const int mM = lane >> 3, iR = lane & 7;
        const int kkb = (mM & 1) * 8 + iR;
#pragma unroll
        for (int g = 0; g < 4; ++g) {
            int nn = wn * 64 + g * 16 + (mM >> 1) * 8;
            uint32_t off = (uint32_t)(kkb * 256 + nn * 2);
            boff[g] = off ^ ((kkb & 7) << 4);
        }
    }

    float acc[8][4];
#pragma unroll
    for (int t = 0; t < 8; ++t)
#pragma unroll
        for (int e = 0; e < 4; ++e) acc[t][e] = 0.0f;
    float dr0 = 0.0f, dr1 = 0.0f;

    // ---- prologue: fill STAGES-1 stages ----
#pragma unroll
    for (int s = 0; s < STAGES - 1; ++s) {
        uint32_t sb = su + s * STAGE_BYTES;
        size_t kf = (size_t)s * BK;
        cp16(sb + soA0, gA0 + kf);
        cp16(sb + soA1, gA1 + kf);
        cp16(sb + 8192 + soB0, gB0 + kf * KDIM);
        cp16(sb + 8192 + soB1, gB1 + kf * KDIM);
        CP_COMMIT();
    }

    // ---- main loop ----
#pragma unroll 4
    for (int it = 0; it < NIT; ++it) {
        CP_WAIT2();
        __syncthreads();
        const char* stp = smem + (it & (STAGES - 1)) * STAGE_BYTES;
        const uint32_t bbase = su + (uint32_t)((it & (STAGES - 1)) * STAGE_BYTES) + 8192;

#pragma unroll
        for (int kq = 0; kq < 2; ++kq) {
            float2 fA[4];
#pragma unroll
            for (int q = 0; q < 4; ++q)
                fA[q] = *reinterpret_cast<const float2*>(stp + aoff[kq][q]);
            dr0 += (fA[0].x + fA[0].y) + (fA[2].x + fA[2].y);
            dr1 += (fA[1].x + fA[1].y) + (fA[3].x + fA[3].y);
            uint32_t ra[4];
#pragma unroll
            for (int q = 0; q < 4; ++q) ra[q] = cvt_bf2(fA[q]);

#pragma unroll
            for (int g = 0; g < 4; ++g) {
                uint32_t b0, b1, b2, b3;
                ldmx4t(b0, b1, b2, b3, bbase + kq * 4096 + boff[g]);
                mma16816(acc[2 * g], ra, b0, b1);
                mma16816(acc[2 * g + 1], ra, b2, b3);
            }
        }

        int nxt = it + (STAGES - 1);
        if (nxt < NIT) {
            uint32_t sb = su + (nxt & (STAGES - 1)) * STAGE_BYTES;
            size_t kf = (size_t)nxt * BK;
            cp16(sb + soA0, gA0 + kf);
            cp16(sb + soA1, gA1 + kf);
            cp16(sb + 8192 + soB0, gB0 + kf * KDIM);
            cp16(sb + 8192 + soB1, gB1 + kf * KDIM);
        }
        CP_COMMIT();
    }

    // ---- partial row sums of A (exact fp32; wn==0 warps only) ----
    if (wn == 0) {
        float s0 = dr0, s1 = dr1;
        s0 += __shfl_xor_sync(0xffffffffu, s0, 1);
        s0 += __shfl_xor_sync(0xffffffffu, s0, 2);
        s1 += __shfl_xor_sync(0xffffffffu, s1, 1);
        s1 += __shfl_xor_sync(0xffffffffu, s1, 2);
        if ((lane & 3) == 0) {
            atomicAdd(&g_d[blockRow + r0], s0);
            atomicAdd(&g_d[blockRow + r0 + 8], s1);
        }
    }

    // ---- colsum(M) and diag = sum_i C[i][j]*M[i][j] (partial over K half) ----
#pragma unroll
    for (int t = 0; t < 8; ++t) {
        const int cbase = wn * 64 + t * 8 + cb;
        const int row = blockRow + r0;
        float2 c0 = *reinterpret_cast<const float2*>(C + (size_t)row * KDIM + cbase);
        float2 c1 = *reinterpret_cast<const float2*>(C + (size_t)(row + 8) * KDIM + cbase);
        float cs0 = acc[t][0] + acc[t][2];
        float cs1 = acc[t][1] + acc[t][3];
        float ds0 = c0.x * acc[t][0] + c1.x * acc[t][2];
        float ds1 = c0.y * acc[t][1] + c1.y * acc[t][3];
#pragma unroll
        for (int o = 4; o <= 16; o <<= 1) {
            cs0 += __shfl_xor_sync(0xffffffffu, cs0, o);
            cs1 += __shfl_xor_sync(0xffffffffu, cs1, o);
            ds0 += __shfl_xor_sync(0xffffffffu, ds0, o);
            ds1 += __shfl_xor_sync(0xffffffffu, ds1, o);
        }
        if ((lane >> 2) == 0) {
            atomicAdd(&scol[cbase], cs0);
            atomicAdd(&scol[cbase + 1], cs1);
            atomicAdd(&sdiag[cbase], ds0);
            atomicAdd(&sdiag[cbase + 1], ds1);
        }
    }
    __syncthreads();
    if (tid < KDIM) {
        atomicAdd(&g_col[tid], scol[tid]);
        atomicAdd(&g_diag[tid], sdiag[tid]);
    }

    // ---- last CTA: sA, h_part, entropy, output ----
    if (tid == 0) {
        __threadfence();
        int c = atomicAdd(&g_cnt, 1);
        is_last = (c == NCTA - 1);
    }
    __syncthreads();
    if (is_last) {
        // sA = sum(g_d), hpart = sum(g_d * g_h2)
        float a1 = 0.0f, a2 = 0.0f;
        for (int i = tid; i < N_FIX; i += 256) {
            float d = __ldcg(&g_d[i]);
            a1 += d * __ldcg(&g_h2[i]);
            a2 += d;
        }
#pragma unroll
        for (int o = 16; o > 0; o >>= 1) {
            a1 += __shfl_xor_sync(0xffffffffu, a1, o);
            a2 += __shfl_xor_sync(0xffffffffu, a2, o);
        }
        if (lane == 0) { swarp[wid] = a1; scol[wid] = a2; }
        __syncthreads();
        float hp = 0.0f, sA = 0.0f;
#pragma unroll
        for (int w = 0; w < 8; ++w) { hp += swarp[w]; sA += scol[w]; }

        float t = 0.0f;
        if (tid < KDIM) {
            float dg = __ldcg(&g_diag[tid]);
            float cl = __ldcg(&g_col[tid]);
            t = dg * log2f(cl / sA + 1e-40f);
        }
#pragma unroll
        for (int o = 16; o > 0; o >>= 1) t += __shfl_xor_sync(0xffffffffu, t, o);
        __syncthreads();
        if (lane == 0) sdiag[wid] = t;
        __syncthreads();
        if (tid == 0) {
            float total = (sdiag[0] + sdiag[1] + sdiag[2] + sdiag[3]) / sA;
            int fl = flag ? *flag : 20;
            float pw = papra ? *papra : 1.0f;
            if (fl > 10) total += pw * hp;
            out[0] = total;
            if (out_size > 1) out[1] = hp;
        }
    }
}

extern "C" void kernel_launch(void* const* d_in, const int* in_sizes, int n_in,
                              void* d_out, int out_size) {
    const float* A = (const float*)d_in[0];
    const float* C = (const float*)d_in[1];
    const float* H = (const float*)d_in[2];
    const float* papra = (n_in > 3) ? (const float*)d_in[3] : nullptr;
    const int* flag = (n_in > 4) ? (const int*)d_in[4] : nullptr;

    cudaFuncSetAttribute(k_gemm, cudaFuncAttributeMaxDynamicSharedMemorySize, SMEM_BYTES);

    k_prep<<<N_FIX / 32, 256>>>(C, H);
    k_gemm<<<NCTA, 256, SMEM_BYTES>>>(A, C, papra, flag, (float*)d_out, out_size);
}

// round 10
// speedup vs baseline: 1.6791x; 1.0445x over previous
#include <cuda_runtime.h>
#include <cuda_bf16.h>
#include <math.h>
#include <stdint.h>

// Fixed problem shape: n=8192, k=128, h=128
#define N_FIX 8192
#define KDIM 128
#define BM 128
#define BK 32
#define KSPLIT 4
#define KQ (N_FIX / KSPLIT)           // 2048
#define NIT (KQ / BK)                 // 64 iterations per CTA
#define NCTA ((N_FIX / BM) * KSPLIT)  // 256
#define STAGES 4
#define STAGE_BYTES 24576             // 16KB A (128x32 fp32) + 8KB B (32x128 bf16)
#define BOFF_IN_STAGE 16384
#define SMEM_BYTES (STAGES * STAGE_BYTES)  // 96KB

// ---------------- device scratch ----------------
__device__ __align__(16) __nv_bfloat16 g_Cb[(size_t)N_FIX * KDIM];
__device__ float g_d[N_FIX];     // row sums of A (atomic, KSPLIT partials)
__device__ float g_h2[N_FIX];    // ||H_i||^2
__device__ float g_col[KDIM];
__device__ float g_diag[KDIM];
__device__ int g_cnt;

// ---------------- helpers ----------------
__device__ __forceinline__ uint32_t smem_u32(const void* p) {
    uint32_t a;
    asm("{ .reg .u64 t; cvta.to.shared.u64 t, %1; cvt.u32.u64 %0, t; }" : "=r"(a) : "l"(p));
    return a;
}
__device__ __forceinline__ void cp16(uint32_t saddr, const void* gp) {
    unsigned long long g = __cvta_generic_to_global(gp);
    asm volatile("cp.async.cg.shared.global [%0], [%1], 16;" :: "r"(saddr), "l"(g) : "memory");
}
#define CP_COMMIT() asm volatile("cp.async.commit_group;" ::: "memory")
#define CP_WAIT2()  asm volatile("cp.async.wait_group 2;" ::: "memory")

__device__ __forceinline__ uint32_t cvt_bf2(float2 v) {
    uint32_t r;  // low = v.x, high = v.y
    asm("cvt.rn.bf16x2.f32 %0, %1, %2;" : "=r"(r) : "f"(v.y), "f"(v.x));
    return r;
}
__device__ __forceinline__ void ldmx4t(uint32_t& r0, uint32_t& r1, uint32_t& r2,
                                       uint32_t& r3, uint32_t addr) {
    asm volatile("ldmatrix.sync.aligned.m8n8.x4.trans.shared.b16 {%0,%1,%2,%3}, [%4];"
                 : "=r"(r0), "=r"(r1), "=r"(r2), "=r"(r3) : "r"(addr));
}
__device__ __forceinline__ void mma16816(float* d, const uint32_t* a, uint32_t b0,
                                         uint32_t b1) {
    asm volatile(
        "mma.sync.aligned.m16n8k16.row.col.f32.bf16.bf16.f32 "
        "{%0,%1,%2,%3}, {%4,%5,%6,%7}, {%8,%9}, {%0,%1,%2,%3};"
        : "+f"(d[0]), "+f"(d[1]), "+f"(d[2]), "+f"(d[3])
        : "r"(a[0]), "r"(a[1]), "r"(a[2]), "r"(a[3]), "r"(b0), "r"(b1));
}

// ---------------- prep: init, C->bf16, ||H_i||^2 ----------------
__global__ void __launch_bounds__(256) k_prep(const float* __restrict__ C,
                                              const float* __restrict__ H) {
    const int b = blockIdx.x, tid = threadIdx.x;
    if (b == 0) {
        if (tid < KDIM) { g_col[tid] = 0.0f; g_diag[tid] = 0.0f; }
        if (tid == 0) g_cnt = 0;
    }
    if (tid < 32) g_d[b * 32 + tid] = 0.0f;

    size_t base = ((size_t)b * 256 + tid) * 16;
    const float4* src = reinterpret_cast<const float4*>(C + base);
    uint32_t o[8];
#pragma unroll
    for (int q = 0; q < 4; ++q) {
        float4 v = __ldg(&src[q]);
        o[q * 2 + 0] = cvt_bf2(make_float2(v.x, v.y));
        o[q * 2 + 1] = cvt_bf2(make_float2(v.z, v.w));
    }
    uint4* dst = reinterpret_cast<uint4*>(g_Cb + base);
    dst[0] = make_uint4(o[0], o[1], o[2], o[3]);
    dst[1] = make_uint4(o[4], o[5], o[6], o[7]);

    const int row = b * 32 + (tid >> 3);
    const float4* hp = reinterpret_cast<const float4*>(H + (size_t)row * KDIM + (tid & 7) * 16);
    float h2 = 0.0f;
#pragma unroll
    for (int q = 0; q < 4; ++q) {
        float4 v = __ldg(&hp[q]);
        h2 += v.x * v.x + v.y * v.y + v.z * v.z + v.w * v.w;
    }
    h2 += __shfl_xor_sync(0xffffffffu, h2, 1);
    h2 += __shfl_xor_sync(0xffffffffu, h2, 2);
    h2 += __shfl_xor_sync(0xffffffffu, h2, 4);
    if ((tid & 7) == 0) g_h2[row] = h2;
}

// ---------------- split-K GEMM (BM=128) + fused reductions + final ----------------
__global__ void __launch_bounds__(256, 2) k_gemm(const float* __restrict__ A,
                                                 const float* __restrict__ C,
                                                 const float* __restrict__ papra,
                                                 const int* __restrict__ flag,
                                                 float* __restrict__ out, int out_size) {
    extern __shared__ __align__(1024) char smem[];
    __shared__ float scol[KDIM], sdiag[KDIM], swarp[8];
    __shared__ int is_last;

    const int tid = threadIdx.x, lane = tid & 31, wid = tid >> 5;
    const int wm = wid & 3, wn = wid >> 2;        // 4 M-warps (m32) x 2 N-warps (n64)
    const int rb = blockIdx.x >> 2;               // row block 0..63
    const int kh = blockIdx.x & 3;                // K quarter
    const int blockRow = rb * BM;
    const int kbase = kh * KQ;
    const uint32_t su = smem_u32(smem);

    if (tid < KDIM) { scol[tid] = 0.0f; sdiag[tid] = 0.0f; }

    // ---- cp.async mapping: A 4 chunks/thread, B 2 chunks/thread ----
    // A: 128 rows x 128B; chunk ch = tid + 256q -> rA = (tid>>3)+32q, cA = tid&7
    const int rA0 = tid >> 3, cA0 = tid & 7;
    const uint32_t soA0 = (uint32_t)(tid * 16) ^ ((rA0 & 7) << 4);
    const float* gA0 = A + (size_t)(blockRow + rA0) * N_FIX + kbase + cA0 * 4;
    // B: 32 k x 256B; chunk ch = tid + 256q -> kB = (tid>>4)+16q, cB = tid&15
    const int kB0 = tid >> 4, cB0 = tid & 15;
    const uint32_t soB0 = (uint32_t)(BOFF_IN_STAGE + tid * 16) ^ ((kB0 & 7) << 4);
    const __nv_bfloat16* gB0 = g_Cb + (size_t)(kbase + kB0) * KDIM + cB0 * 8;

    // ---- A fragment offsets (mt=0 base): rr = wm*32 + (lane>>2) + 8*(q&1)
    const int r0 = wm * 32 + (lane >> 2);
    const int cb = (lane & 3) * 2;
    uint32_t aoff[2][4];
#pragma unroll
    for (int kq = 0; kq < 2; ++kq) {
        int cc = kq * 16 + cb;
#pragma unroll
        for (int q = 0; q < 4; ++q) {
            int rr = r0 + ((q & 1) ? 8 : 0);
            int c2 = cc + ((q & 2) ? 8 : 0);
            uint32_t off = (uint32_t)(rr * 128 + c2 * 4);
            aoff[kq][q] = off ^ ((rr & 7) << 4);
        }
    }
    // ---- B LDSM offsets
    uint32_t boff[4];
    {
        const int mM = lane >> 3, iR = lane & 7;
        const int kkb = (mM & 1) * 8 + iR;
#pragma unroll
        for (int g = 0; g < 4; ++g) {
            int nn = wn * 64 + g * 16 + (mM >> 1) * 8;
            uint32_t off = (uint32_t)(BOFF_IN_STAGE + kkb * 256 + nn * 2);
            boff[g] = off ^ ((kkb & 7) << 4);
        }
    }

    float acc[2][8][4];
#pragma unroll
    for (int mt = 0; mt < 2; ++mt)
#pragma unroll
        for (int t = 0; t < 8; ++t)
#pragma unroll
            for (int e = 0; e < 4; ++e) acc[mt][t][e] = 0.0f;
    float dr[4] = {0.f, 0.f, 0.f, 0.f};  // rows r0 + {0,8,16,24}

    // ---- prologue ----
#pragma unroll
    for (int s = 0; s < STAGES - 1; ++s) {
        uint32_t sb = su + s * STAGE_BYTES;
        size_t kf = (size_t)s * BK;
#pragma unroll
        for (int q = 0; q < 4; ++q)
            cp16(sb + soA0 + q * 4096, gA0 + kf + (size_t)q * 32 * N_FIX);
#pragma unroll
        for (int q = 0; q < 2; ++q)
            cp16(sb + soB0 + q * 4096, gB0 + (kf + (size_t)q * 16) * KDIM);
        CP_COMMIT();
    }

    // ---- main loop ----
    for (int it = 0; it < NIT; ++it) {
        CP_WAIT2();
        __syncthreads();
        const uint32_t stg = su + (uint32_t)((it & (STAGES - 1)) * STAGE_BYTES);

#pragma unroll
        for (int kq = 0; kq < 2; ++kq) {
            uint32_t ra[2][4];
#pragma unroll
            for (int mt = 0; mt < 2; ++mt) {
                float2 fA[4];
#pragma unroll
                for (int q = 0; q < 4; ++q)
                    fA[q] = *reinterpret_cast<const float2*>(
                        smem + (stg - su) + aoff[kq][q] + mt * 2048);
                dr[2 * mt + 0] += (fA[0].x + fA[0].y) + (fA[2].x + fA[2].y);
                dr[2 * mt + 1] += (fA[1].x + fA[1].y) + (fA[3].x + fA[3].y);
#pragma unroll
                for (int q = 0; q < 4; ++q) ra[mt][q] = cvt_bf2(fA[q]);
            }
#pragma unroll
            for (int g = 0; g < 4; ++g) {
                uint32_t b0, b1, b2, b3;
                ldmx4t(b0, b1, b2, b3, stg + boff[g] + kq * 4096);
                mma16816(acc[0][2 * g], ra[0], b0, b1);
                mma16816(acc[0][2 * g + 1], ra[0], b2, b3);
                mma16816(acc[1][2 * g], ra[1], b0, b1);
                mma16816(acc[1][2 * g + 1], ra[1], b2, b3);
            }
        }

        int nxt = it + (STAGES - 1);
        if (nxt < NIT) {
            uint32_t sb = su + (nxt & (STAGES - 1)) * STAGE_BYTES;
            size_t kf = (size_t)nxt * BK;
#pragma unroll
            for (int q = 0; q < 4; ++q)
                cp16(sb + soA0 + q * 4096, gA0 + kf + (size_t)q * 32 * N_FIX);
#pragma unroll
            for (int q = 0; q < 2; ++q)
                cp16(sb + soB0 + q * 4096, gB0 + (kf + (size_t)q * 16) * KDIM);
        }
        CP_COMMIT();
    }

    // ---- partial row sums of A (exact fp32; wn==0 warps only) ----
    if (wn == 0) {
#pragma unroll
        for (int m = 0; m < 4; ++m) {
            float s = dr[m];
            s += __shfl_xor_sync(0xffffffffu, s, 1);
            s += __shfl_xor_sync(0xffffffffu, s, 2);
            if ((lane & 3) == 0) atomicAdd(&g_d[blockRow + r0 + ((m & 1) ? 8 : 0) + (m >> 1) * 16], s);
        }
    }

    // ---- colsum(M) and diag partials ----
#pragma unroll
    for (int mt = 0; mt < 2; ++mt)
#pragma unroll
    for (int t = 0; t < 8; ++t) {
        const int cbase = wn * 64 + t * 8 + cb;
        const int row = blockRow + r0 + mt * 16;
        float2 c0 = *reinterpret_cast<const float2*>(C + (size_t)row * KDIM + cbase);
        float2 c1 = *reinterpret_cast<const float2*>(C + (size_t)(row + 8) * KDIM + cbase);
        float cs0 = acc[mt][t][0] + acc[mt][t][2];
        float cs1 = acc[mt][t][1] + acc[mt][t][3];
        float ds0 = c0.x * acc[mt][t][0] + c1.x * acc[mt][t][2];
        float ds1 = c0.y * acc[mt][t][1] + c1.y * acc[mt][t][3];
#pragma unroll
        for (int o = 4; o <= 16; o <<= 1) {
            cs0 += __shfl_xor_sync(0xffffffffu, cs0, o);
            cs1 += __shfl_xor_sync(0xffffffffu, cs1, o);
            ds0 += __shfl_xor_sync(0xffffffffu, ds0, o);
            ds1 += __shfl_xor_sync(0xffffffffu, ds1, o);
        }
        if ((lane >> 2) == 0) {
            atomicAdd(&scol[cbase], cs0);
            atomicAdd(&scol[cbase + 1], cs1);
            atomicAdd(&sdiag[cbase], ds0);
            atomicAdd(&sdiag[cbase + 1], ds1);
        }
    }
    __syncthreads();
    if (tid < KDIM) {
        atomicAdd(&g_col[tid], scol[tid]);
        atomicAdd(&g_diag[tid], sdiag[tid]);
    }

    // ---- last CTA: sA, h_part, entropy, output ----
    if (tid == 0) {
        __threadfence();
        int c = atomicAdd(&g_cnt, 1);
        is_last = (c == NCTA - 1);
    }
    __syncthreads();
    if (is_last) {
        float a1 = 0.0f, a2 = 0.0f;
        for (int i = tid; i < N_FIX; i += 256) {
            float d = __ldcg(&g_d[i]);
            a1 += d * __ldcg(&g_h2[i]);
            a2 += d;
        }
#pragma unroll
        for (int o = 16; o > 0; o >>= 1) {
            a1 += __shfl_xor_sync(0xffffffffu, a1, o);
            a2 += __shfl_xor_sync(0xffffffffu, a2, o);
        }
        if (lane == 0) { swarp[wid] = a1; scol[wid] = a2; }
        __syncthreads();
        float hp = 0.0f, sA = 0.0f;
#pragma unroll
        for (int w = 0; w < 8; ++w) { hp += swarp[w]; sA += scol[w]; }

        float t = 0.0f;
        if (tid < KDIM) {
            float dg = __ldcg(&g_diag[tid]);
            float cl = __ldcg(&g_col[tid]);
            t = dg * log2f(cl / sA + 1e-40f);
        }
#pragma unroll
        for (int o = 16; o > 0; o >>= 1) t += __shfl_xor_sync(0xffffffffu, t, o);
        __syncthreads();
        if (lane == 0) sdiag[wid] = t;
        __syncthreads();
        if (tid == 0) {
            float total = (sdiag[0] + sdiag[1] + sdiag[2] + sdiag[3]) / sA;
            int fl = flag ? *flag : 20;
            float pw = papra ? *papra : 1.0f;
            if (fl > 10) total += pw * hp;
            out[0] = total;
            if (out_size > 1) out[1] = hp;
        }
    }
}

extern "C" void kernel_launch(void* const* d_in, const int* in_sizes, int n_in,
                              void* d_out, int out_size) {
    const float* A = (const float*)d_in[0];
    const float* C = (const float*)d_in[1];
    const float* H = (const float*)d_in[2];
    const float* papra = (n_in > 3) ? (const float*)d_in[3] : nullptr;
    const int* flag = (n_in > 4) ? (const int*)d_in[4] : nullptr;

    cudaFuncSetAttribute(k_gemm, cudaFuncAttributeMaxDynamicSharedMemorySize, SMEM_BYTES);

    k_prep<<<N_FIX / 32, 256>>>(C, H);
    k_gemm<<<NCTA, 256, SMEM_BYTES>>>(A, C, papra, flag, (float*)d_out, out_size);
}

// round 11
// speedup vs baseline: 1.9591x; 1.1667x over previous
#include <cuda_runtime.h>
#include <cuda_bf16.h>
#include <math.h>
#include <stdint.h>

// Fixed problem shape: n=8192, k=128, h=128
#define N_FIX 8192
#define KDIM 128
#define BM 128
#define BK 32
#define KSPLIT 4
#define KQ (N_FIX / KSPLIT)           // 2048
#define NIT (KQ / BK)                 // 64 iterations per CTA
#define NCTA ((N_FIX / BM) * KSPLIT)  // 256
#define STAGES 4
#define STAGE_BYTES 24576             // 16KB A (128x32 fp32) + 8KB B (32x128 bf16)
#define BOFF_IN_STAGE 16384
#define SMEM_BYTES (STAGES * STAGE_BYTES)  // 96KB

// ---------------- device scratch ----------------
__device__ __align__(16) __nv_bfloat16 g_Cb[(size_t)N_FIX * KDIM];
__device__ float g_d[N_FIX];     // row sums of A (atomic, KSPLIT partials)
__device__ float g_h2[N_FIX];    // ||H_i||^2
__device__ float g_col[KDIM];
__device__ float g_diag[KDIM];
__device__ int g_cnt;

// ---------------- helpers ----------------
__device__ __forceinline__ uint32_t smem_u32(const void* p) {
    uint32_t a;
    asm("{ .reg .u64 t; cvta.to.shared.u64 t, %1; cvt.u32.u64 %0, t; }" : "=r"(a) : "l"(p));
    return a;
}
__device__ __forceinline__ void cp16(uint32_t saddr, const void* gp) {
    unsigned long long g = __cvta_generic_to_global(gp);
    asm volatile("cp.async.cg.shared.global [%0], [%1], 16;" :: "r"(saddr), "l"(g) : "memory");
}
#define CP_COMMIT() asm volatile("cp.async.commit_group;" ::: "memory")
#define CP_WAIT2()  asm volatile("cp.async.wait_group 2;" ::: "memory")

__device__ __forceinline__ uint32_t cvt_bf2(float2 v) {
    uint32_t r;  // low = v.x, high = v.y
    asm("cvt.rn.bf16x2.f32 %0, %1, %2;" : "=r"(r) : "f"(v.y), "f"(v.x));
    return r;
}
__device__ __forceinline__ void ldmx4t(uint32_t& r0, uint32_t& r1, uint32_t& r2,
                                       uint32_t& r3, uint32_t addr) {
    asm volatile("ldmatrix.sync.aligned.m8n8.x4.trans.shared.b16 {%0,%1,%2,%3}, [%4];"
                 : "=r"(r0), "=r"(r1), "=r"(r2), "=r"(r3) : "r"(addr));
}
__device__ __forceinline__ void mma16816(float* d, const uint32_t* a, uint32_t b0,
                                         uint32_t b1) {
    asm volatile(
        "mma.sync.aligned.m16n8k16.row.col.f32.bf16.bf16.f32 "
        "{%0,%1,%2,%3}, {%4,%5,%6,%7}, {%8,%9}, {%0,%1,%2,%3};"
        : "+f"(d[0]), "+f"(d[1]), "+f"(d[2]), "+f"(d[3])
        : "r"(a[0]), "r"(a[1]), "r"(a[2]), "r"(a[3]), "r"(b0), "r"(b1));
}

// ---------------- prep: init, C->bf16, ||H_i||^2 ----------------
__global__ void __launch_bounds__(256) k_prep(const float* __restrict__ C,
                                              const float* __restrict__ H) {
    const int b = blockIdx.x, tid = threadIdx.x;
    if (b == 0) {
        if (tid < KDIM) { g_col[tid] = 0.0f; g_diag[tid] = 0.0f; }
        if (tid == 0) g_cnt = 0;
    }
    if (tid < 32) g_d[b * 32 + tid] = 0.0f;

    size_t base = ((size_t)b * 256 + tid) * 16;
    const float4* src = reinterpret_cast<const float4*>(C + base);
    uint32_t o[8];
#pragma unroll
    for (int q = 0; q < 4; ++q) {
        float4 v = __ldg(&src[q]);
        o[q * 2 + 0] = cvt_bf2(make_float2(v.x, v.y));
        o[q * 2 + 1] = cvt_bf2(make_float2(v.z, v.w));
    }
    uint4* dst = reinterpret_cast<uint4*>(g_Cb + base);
    dst[0] = make_uint4(o[0], o[1], o[2], o[3]);
    dst[1] = make_uint4(o[4], o[5], o[6], o[7]);

    const int row = b * 32 + (tid >> 3);
    const float4* hp = reinterpret_cast<const float4*>(H + (size_t)row * KDIM + (tid & 7) * 16);
    float h2 = 0.0f;
#pragma unroll
    for (int q = 0; q < 4; ++q) {
        float4 v = __ldg(&hp[q]);
        h2 += v.x * v.x + v.y * v.y + v.z * v.z + v.w * v.w;
    }
    h2 += __shfl_xor_sync(0xffffffffu, h2, 1);
    h2 += __shfl_xor_sync(0xffffffffu, h2, 2);
    h2 += __shfl_xor_sync(0xffffffffu, h2, 4);
    if ((tid & 7) == 0) g_h2[row] = h2;
}

// ---------------- split-K GEMM (BM=128) + fused reductions + final ----------------
__global__ void __launch_bounds__(256, 2) k_gemm(const float* __restrict__ A,
                                                 const float* __restrict__ C,
                                                 const float* __restrict__ papra,
                                                 const int* __restrict__ flag,
                                                 float* __restrict__ out, int out_size) {
    extern __shared__ __align__(1024) char smem[];
    __shared__ float scol[KDIM], sdiag[KDIM], swarp[8];
    __shared__ int is_last;

    const int tid = threadIdx.x, lane = tid & 31, wid = tid >> 5;
    const int wm = wid & 3, wn = wid >> 2;        // 4 M-warps (m32) x 2 N-warps (n64)
    const int rb = blockIdx.x >> 2;               // row block 0..63
    const int kh = blockIdx.x & 3;                // K quarter
    const int blockRow = rb * BM;
    const int kbase = kh * KQ;
    const uint32_t su = smem_u32(smem);

    if (tid < KDIM) { scol[tid] = 0.0f; sdiag[tid] = 0.0f; }

    // ---- cp.async mapping: A 4 chunks/thread, B 2 chunks/thread ----
    // A tile: 128 rows x 128B, 32B-granular XOR swizzle: addr = r*128 + (c ^ ((r&3)<<5))
    const int rA0 = tid >> 3, cA0 = tid & 7;
    const uint32_t soA0 = (uint32_t)(rA0 * 128 + ((cA0 * 16) ^ ((rA0 & 3) << 5)));
    const float* gA0 = A + (size_t)(blockRow + rA0) * N_FIX + kbase + cA0 * 4;
    // B: 32 k x 256B; 16B XOR swizzle (LDSM-friendly, verified conflict-free)
    const int kB0 = tid >> 4, cB0 = tid & 15;
    const uint32_t soB0 = (uint32_t)(BOFF_IN_STAGE + kB0 * 256 + ((cB0 * 16) ^ ((kB0 & 7) << 4)));
    const __nv_bfloat16* gB0 = g_Cb + (size_t)(kbase + kB0) * KDIM + cB0 * 8;

    // ---- A fragment offsets: rr = wm*32 + (lane>>2) + 8*(q&1); 32B-window XOR
    const int r0 = wm * 32 + (lane >> 2);
    const int cb = (lane & 3) * 2;
    uint32_t aoff[2][4];
#pragma unroll
    for (int kq = 0; kq < 2; ++kq) {
#pragma unroll
        for (int q = 0; q < 4; ++q) {
            int rr = r0 + ((q & 1) ? 8 : 0);
            uint32_t coff = (uint32_t)(kq * 64 + cb * 4 + ((q & 2) ? 32 : 0));
            aoff[kq][q] = (uint32_t)(rr * 128) + (coff ^ ((rr & 3) << 5));
        }
    }
    // ---- B LDSM offsets
    uint32_t boff[4];
    {
        const int mM = lane >> 3, iR = lane & 7;
        const int kkb = (mM & 1) * 8 + iR;
#pragma unroll
        for (int g = 0; g < 4; ++g) {
            int nn = wn * 64 + g * 16 + (mM >> 1) * 8;
            uint32_t off = (uint32_t)(kkb * 256 + nn * 2);
            boff[g] = (uint32_t)BOFF_IN_STAGE + (off ^ ((kkb & 7) << 4));
        }
    }

    float acc[2][8][4];
#pragma unroll
    for (int mt = 0; mt < 2; ++mt)
#pragma unroll
        for (int t = 0; t < 8; ++t)
#pragma unroll
            for (int e = 0; e < 4; ++e) acc[mt][t][e] = 0.0f;
    float dr[4] = {0.f, 0.f, 0.f, 0.f};  // rows r0 + {0,8,16,24}

    // ---- prologue ----
#pragma unroll
    for (int s = 0; s < STAGES - 1; ++s) {
        uint32_t sb = su + s * STAGE_BYTES;
        size_t kf = (size_t)s * BK;
#pragma unroll
        for (int q = 0; q < 4; ++q)
            cp16(sb + soA0 + q * 4096, gA0 + kf + (size_t)q * 32 * N_FIX);
#pragma unroll
        for (int q = 0; q < 2; ++q)
            cp16(sb + soB0 + q * 4096, gB0 + (kf + (size_t)q * 16) * KDIM);
        CP_COMMIT();
    }

    // ---- main loop ----
    for (int it = 0; it < NIT; ++it) {
        CP_WAIT2();
        __syncthreads();
        const uint32_t stg = (uint32_t)((it & (STAGES - 1)) * STAGE_BYTES);

#pragma unroll
        for (int kq = 0; kq < 2; ++kq) {
            uint32_t ra[2][4];
#pragma unroll
            for (int mt = 0; mt < 2; ++mt) {
                float2 fA[4];
#pragma unroll
                for (int q = 0; q < 4; ++q)
                    fA[q] = *reinterpret_cast<const float2*>(
                        smem + stg + aoff[kq][q] + mt * 2048);
                dr[2 * mt + 0] += (fA[0].x + fA[0].y) + (fA[2].x + fA[2].y);
                dr[2 * mt + 1] += (fA[1].x + fA[1].y) + (fA[3].x + fA[3].y);
#pragma unroll
                for (int q = 0; q < 4; ++q) ra[mt][q] = cvt_bf2(fA[q]);
            }
#pragma unroll
            for (int g = 0; g < 4; ++g) {
                uint32_t b0, b1, b2, b3;
                ldmx4t(b0, b1, b2, b3, su + stg + boff[g] + kq * 4096);
                mma16816(acc[0][2 * g], ra[0], b0, b1);
                mma16816(acc[0][2 * g + 1], ra[0], b2, b3);
                mma16816(acc[1][2 * g], ra[1], b0, b1);
                mma16816(acc[1][2 * g + 1], ra[1], b2, b3);
            }
        }

        int nxt = it + (STAGES - 1);
        if (nxt < NIT) {
            uint32_t sb = su + (nxt & (STAGES - 1)) * STAGE_BYTES;
            size_t kf = (size_t)nxt * BK;
#pragma unroll
            for (int q = 0; q < 4; ++q)
                cp16(sb + soA0 + q * 4096, gA0 + kf + (size_t)q * 32 * N_FIX);
#pragma unroll
            for (int q = 0; q < 2; ++q)
                cp16(sb + soB0 + q * 4096, gB0 + (kf + (size_t)q * 16) * KDIM);
        }
        CP_COMMIT();
    }

    // ---- partial row sums of A (exact fp32; wn==0 warps only) ----
    if (wn == 0) {
#pragma unroll
        for (int m = 0; m < 4; ++m) {
            float s = dr[m];
            s += __shfl_xor_sync(0xffffffffu, s, 1);
            s += __shfl_xor_sync(0xffffffffu, s, 2);
            if ((lane & 3) == 0) atomicAdd(&g_d[blockRow + r0 + ((m & 1) ? 8 : 0) + (m >> 1) * 16], s);
        }
    }

    // ---- colsum(M) and diag partials ----
#pragma unroll
    for (int mt = 0; mt < 2; ++mt)
#pragma unroll
    for (int t = 0; t < 8; ++t) {
        const int cbase = wn * 64 + t * 8 + cb;
        const int row = blockRow + r0 + mt * 16;
        float2 c0 = *reinterpret_cast<const float2*>(C + (size_t)row * KDIM + cbase);
        float2 c1 = *reinterpret_cast<const float2*>(C + (size_t)(row + 8) * KDIM + cbase);
        float cs0 = acc[mt][t][0] + acc[mt][t][2];
        float cs1 = acc[mt][t][1] + acc[mt][t][3];
        float ds0 = c0.x * acc[mt][t][0] + c1.x * acc[mt][t][2];
        float ds1 = c0.y * acc[mt][t][1] + c1.y * acc[mt][t][3];
#pragma unroll
        for (int o = 4; o <= 16; o <<= 1) {
            cs0 += __shfl_xor_sync(0xffffffffu, cs0, o);
            cs1 += __shfl_xor_sync(0xffffffffu, cs1, o);
            ds0 += __shfl_xor_sync(0xffffffffu, ds0, o);
            ds1 += __shfl_xor_sync(0xffffffffu, ds1, o);
        }
        if ((lane >> 2) == 0) {
            atomicAdd(&scol[cbase], cs0);
            atomicAdd(&scol[cbase + 1], cs1);
            atomicAdd(&sdiag[cbase], ds0);
            atomicAdd(&sdiag[cbase + 1], ds1);
        }
    }
    __syncthreads();
    if (tid < KDIM) {
        atomicAdd(&g_col[tid], scol[tid]);
        atomicAdd(&g_diag[tid], sdiag[tid]);
    }

    // ---- last CTA: sA, h_part, entropy, output ----
    if (tid == 0) {
        __threadfence();
        int c = atomicAdd(&g_cnt, 1);
        is_last = (c == NCTA - 1);
    }
    __syncthreads();
    if (is_last) {
        float a1 = 0.0f, a2 = 0.0f;
        for (int i = tid; i < N_FIX; i += 256) {
            float d = __ldcg(&g_d[i]);
            a1 += d * __ldcg(&g_h2[i]);
            a2 += d;
        }
#pragma unroll
        for (int o = 16; o > 0; o >>= 1) {
            a1 += __shfl_xor_sync(0xffffffffu, a1, o);
            a2 += __shfl_xor_sync(0xffffffffu, a2, o);
        }
        if (lane == 0) { swarp[wid] = a1; scol[wid] = a2; }
        __syncthreads();
        float hp = 0.0f, sA = 0.0f;
#pragma unroll
        for (int w = 0; w < 8; ++w) { hp += swarp[w]; sA += scol[w]; }

        float t = 0.0f;
        if (tid < KDIM) {
            float dg = __ldcg(&g_diag[tid]);
            float cl = __ldcg(&g_col[tid]);
            t = dg * log2f(cl / sA + 1e-40f);
        }
#pragma unroll
        for (int o = 16; o > 0; o >>= 1) t += __shfl_xor_sync(0xffffffffu, t, o);
        __syncthreads();
        if (lane == 0) sdiag[wid] = t;
        __syncthreads();
        if (tid == 0) {
            float total = (sdiag[0] + sdiag[1] + sdiag[2] + sdiag[3]) / sA;
            int fl = flag ? *flag : 20;
            float pw = papra ? *papra : 1.0f;
            if (fl > 10) total += pw * hp;
            out[0] = total;
            if (out_size > 1) out[1] = hp;
        }
    }
}

extern "C" void kernel_launch(void* const* d_in, const int* in_sizes, int n_in,
                              void* d_out, int out_size) {
    const float* A = (const float*)d_in[0];
    const float* C = (const float*)d_in[1];
    const float* H = (const float*)d_in[2];
    const float* papra = (n_in > 3) ? (const float*)d_in[3] : nullptr;
    const int* flag = (n_in > 4) ? (const int*)d_in[4] : nullptr;

    cudaFuncSetAttribute(k_gemm, cudaFuncAttributeMaxDynamicSharedMemorySize, SMEM_BYTES);

    k_prep<<<N_FIX / 32, 256>>>(C, H);
    k_gemm<<<NCTA, 256, SMEM_BYTES>>>(A, C, papra, flag, (float*)d_out, out_size);
}